// round 1
// baseline (speedup 1.0000x reference)
#include <cuda_runtime.h>

// Depthwise 3x3 lateral conv (center tap = 0) + residual, NHWC f32.
// x: [32,56,56,256], kernel: [3,3,256], out: [32,56,56,256]
//
// Mapping: thread.x = c4 (0..63, 4 channels as float4), thread.y = w-within-block (0..3)
// grid: (W/4=14, H=56, B=32). All global loads/stores are 16B coalesced.
// The 3x3x256 kernel (9 KB) is staged in shared memory once per block.

#define H 56
#define W 56
#define C 256
#define C4 (C / 4)   // 64

__global__ __launch_bounds__(256) void contour_kernel(
    const float* __restrict__ x,
    const float* __restrict__ kern,
    float* __restrict__ out)
{
    __shared__ float4 sk[9 * C4];  // 9 taps x 64 float4 = 9 KB

    const int tid = threadIdx.y * blockDim.x + threadIdx.x;  // 0..255
    // cooperative load of the full kernel: 9*64 = 576 float4, 256 threads
    const float4* kern4 = reinterpret_cast<const float4*>(kern);
    for (int i = tid; i < 9 * C4; i += 256) {
        sk[i] = kern4[i];
    }
    __syncthreads();

    const int c4 = threadIdx.x;                 // 0..63
    const int w  = blockIdx.x * 4 + threadIdx.y; // 0..55
    const int h  = blockIdx.y;
    const int b  = blockIdx.z;

    const float4* xin = reinterpret_cast<const float4*>(x);
    float4* o = reinterpret_cast<float4*>(out);

    const size_t img_base = (size_t)b * H * W * C4;

    float4 acc = make_float4(0.f, 0.f, 0.f, 0.f);

    #pragma unroll
    for (int dh = -1; dh <= 1; dh++) {
        const int hh = h + dh;
        if (hh < 0 || hh >= H) continue;
        const size_t row_base = img_base + (size_t)hh * W * C4;
        #pragma unroll
        for (int dw = -1; dw <= 1; dw++) {
            if (dh == 0 && dw == 0) continue;   // center tap excluded
            const int ww = w + dw;
            if (ww < 0 || ww >= W) continue;
            const float4 v = xin[row_base + (size_t)ww * C4 + c4];
            const float4 k = sk[((dh + 1) * 3 + (dw + 1)) * C4 + c4];
            acc.x = fmaf(v.x, k.x, acc.x);
            acc.y = fmaf(v.y, k.y, acc.y);
            acc.z = fmaf(v.z, k.z, acc.z);
            acc.w = fmaf(v.w, k.w, acc.w);
        }
    }

    // residual add (center pixel)
    const size_t ctr = img_base + ((size_t)h * W + w) * C4 + c4;
    const float4 c = xin[ctr];
    acc.x += c.x; acc.y += c.y; acc.z += c.z; acc.w += c.w;

    o[ctr] = acc;
}

extern "C" void kernel_launch(void* const* d_in, const int* in_sizes, int n_in,
                              void* d_out, int out_size)
{
    const float* x    = (const float*)d_in[0];   // [32,56,56,256]
    const float* kern = (const float*)d_in[1];   // [3,3,256]
    float* out        = (float*)d_out;

    dim3 block(C4, 4, 1);        // 64 x 4 = 256 threads
    dim3 grid(W / 4, H, 32);     // 14 x 56 x 32
    contour_kernel<<<grid, block>>>(x, kern, out);
}

// round 2
// speedup vs baseline: 1.8343x; 1.8343x over previous
#include <cuda_runtime.h>

// Depthwise 3x3 lateral conv (center tap excluded) + residual, NHWC f32.
// x: [32,56,56,256], kernel: [3,3,256], out: [32,56,56,256]
//
// Register-tiled: each thread owns 4 channels (float4 at c4) and computes an
// HR=2 x WR=4 patch of outputs. The 3x3 kernel taps live in registers with the
// center tap replaced by 1.0, which folds the residual add into the conv.
// Per thread: 24 x-loads + 9 kernel loads + 8 stores for 8 outputs
// (~5 L1 transactions/output vs ~18 in the naive version).

#define H 56
#define W 56
#define C 256
#define C4 (C / 4)   // 64
#define HR 2
#define WR 4

__global__ __launch_bounds__(128, 4) void contour_kernel(
    const float* __restrict__ x,
    const float* __restrict__ kern,
    float* __restrict__ out)
{
    const int c4 = threadIdx.x;                          // 0..63
    const int wb = blockIdx.x * 8 + threadIdx.y * 4;     // 0,4,...,52
    const int hb = blockIdx.y * HR;                      // 0,2,...,54
    const int b  = blockIdx.z;

    const float4* __restrict__ xin = reinterpret_cast<const float4*>(x);
    const float4* __restrict__ k4  = reinterpret_cast<const float4*>(kern);
    float4* __restrict__ o = reinterpret_cast<float4*>(out);

    // Kernel taps -> registers. Center tap := 1.0 (residual fold).
    float4 kreg[9];
    #pragma unroll
    for (int t = 0; t < 9; t++) kreg[t] = k4[t * C4 + c4];
    kreg[4] = make_float4(1.f, 1.f, 1.f, 1.f);

    const size_t img = (size_t)b * H * W * C4;

    float4 acc[HR][WR];
    #pragma unroll
    for (int r = 0; r < HR; r++)
        #pragma unroll
        for (int j = 0; j < WR; j++)
            acc[r][j] = make_float4(0.f, 0.f, 0.f, 0.f);

    #pragma unroll
    for (int ih = 0; ih < HR + 2; ih++) {
        const int row = hb - 1 + ih;
        if (row < 0 || row >= H) continue;
        const size_t rb = img + (size_t)row * W * C4 + c4;

        // load 6 consecutive-w float4s for this input row (OOB -> 0)
        float4 v[WR + 2];
        #pragma unroll
        for (int j = 0; j < WR + 2; j++) {
            const int col = wb - 1 + j;
            v[j] = (col >= 0 && col < W) ? xin[rb + (size_t)col * C4]
                                         : make_float4(0.f, 0.f, 0.f, 0.f);
        }

        #pragma unroll
        for (int r = 0; r < HR; r++) {
            const int kh = ih - r;            // which kernel row this input row feeds
            if (kh < 0 || kh > 2) continue;
            #pragma unroll
            for (int j = 0; j < WR; j++) {
                #pragma unroll
                for (int dw = 0; dw < 3; dw++) {
                    const float4 kk = kreg[kh * 3 + dw];
                    const float4 vv = v[j + dw];
                    acc[r][j].x = fmaf(vv.x, kk.x, acc[r][j].x);
                    acc[r][j].y = fmaf(vv.y, kk.y, acc[r][j].y);
                    acc[r][j].z = fmaf(vv.z, kk.z, acc[r][j].z);
                    acc[r][j].w = fmaf(vv.w, kk.w, acc[r][j].w);
                }
            }
        }
    }

    #pragma unroll
    for (int r = 0; r < HR; r++) {
        const size_t rb = img + (size_t)(hb + r) * W * C4 + c4;
        #pragma unroll
        for (int j = 0; j < WR; j++)
            o[rb + (size_t)(wb + j) * C4] = acc[r][j];
    }
}

extern "C" void kernel_launch(void* const* d_in, const int* in_sizes, int n_in,
                              void* d_out, int out_size)
{
    const float* x    = (const float*)d_in[0];   // [32,56,56,256]
    const float* kern = (const float*)d_in[1];   // [3,3,256]
    float* out        = (float*)d_out;

    dim3 block(C4, 2, 1);          // 64 x 2 = 128 threads; block covers 8 w
    dim3 grid(W / 8, H / HR, 32);  // 7 x 28 x 32
    contour_kernel<<<grid, block>>>(x, kern, out);
}